// round 13
// baseline (speedup 1.0000x reference)
#include <cuda_runtime.h>
#include <cuda_fp16.h>

#define Nn   50000
#define Ee   800000
#define F_IN 128
#define HID  64
#define Ll   3
#define Gg   512
#define BN_EPS 1e-5f
#define INVN (1.0f / 50000.0f)

#define EDGE_BLOCKS  ((Ee + 255) / 256)            // 3125
#define STATX_BLOCKS 256
#define GEMM_BLOCKS  ((Nn + 127) / 128)            // 391
#define GATHER_GRID  ((Nn + 15) / 16)              // 3125
#define SCAN_T   512
#define SCAN_E   2048
#define SCAN_NB  ((Nn + SCAN_E - 1) / SCAN_E)      // 25

// ---------------- scratch (static device arrays; zero-initialized) ---------
__device__ __align__(16) float  g_h[Nn * HID];     // activations (post-relu)
__device__ __align__(16) __half g_zh[Nn * HID];    // dis-prescaled z, fp16
__device__ __align__(16) float  g_Wp[F_IN * HID];  // folded weight
__device__ __align__(16) float  g_c[HID];          // folded bias row
__device__ __align__(16) float  g_sum[F_IN];       // x stats (zero invariant)
__device__ __align__(16) float  g_sumsq[F_IN];
__device__ __align__(16) float  g_s2[HID];         // h stats (zero invariant)
__device__ __align__(16) float  g_q2[HID];
__device__ int      g_degout[Nn];                  // zero invariant
__device__ int      g_degin[Nn];                   // zero invariant
__device__ float    g_dis[Nn];
__device__ int      g_off[Nn + 1];
__device__ int      g_cursor[Nn];
__device__ int      g_csr[Ee];
__device__ unsigned g_pub[SCAN_NB];                // lookback (zero invariant)
__device__ unsigned g_ctr;                         // last-block ctr (zero inv.)

// ---------------- helpers ----------------------------------------------------
__device__ __forceinline__ void red_add_v4(float* addr, float4 v) {
    asm volatile("red.global.add.v4.f32 [%0], {%1, %2, %3, %4};"
                 :: "l"(addr), "f"(v.x), "f"(v.y), "f"(v.z), "f"(v.w)
                 : "memory");
}

__device__ __forceinline__ float4 h4_to_f4(uint2 u) {
    __half2 a = *(__half2*)&u.x;
    __half2 b = *(__half2*)&u.y;
    float2 fa = __half22float2(a);
    float2 fb = __half22float2(b);
    return make_float4(fa.x, fa.y, fb.x, fb.y);
}

// release-ordered arrive; returns true for the last block of nblocks.
__device__ __forceinline__ bool last_block(unsigned nblocks) {
    unsigned old;
    asm volatile("atom.release.gpu.global.add.u32 %0, [%1], 1;"
                 : "=r"(old) : "l"(&g_ctr) : "memory");
    return old == nblocks - 1u;
}

// BN fold by ONE block (256 threads): Wp = diag(s)W, c = t@W (+blin).
// Resets the stats accumulators (zero invariant). sS/sT: shared scratch >= K.
__device__ __forceinline__ void do_fold(const float* __restrict__ gamma,
                                        const float* __restrict__ beta,
                                        const float* __restrict__ W,
                                        const float* __restrict__ blin,
                                        int K, float* sums, float* sqs,
                                        float* sS, float* sT) {
    int t = threadIdx.x;
    asm volatile("fence.acq_rel.gpu;" ::: "memory");   // one CCTL, last block only
    if (t < K) {
        float mu  = sums[t] * INVN;
        float var = fmaxf(sqs[t] * INVN - mu * mu, 0.f);
        float sc  = gamma[t] * rsqrtf(var + BN_EPS);
        sS[t] = sc;
        sT[t] = beta[t] - mu * sc;
        sums[t] = 0.f;
        sqs[t]  = 0.f;
    }
    __syncthreads();
    for (int i = t; i < K * HID; i += 256)
        g_Wp[i] = sS[i >> 6] * W[i];
    if (t < HID) {
        float c = blin ? blin[t] : 0.f;
        for (int k = 0; k < K; k++) c += sT[k] * W[k * HID + t];
        g_c[t] = c;
    }
    if (t == 0) g_ctr = 0;   // plain store; next kernel boundary publishes
}

// ---------------- chain B: edge degree count ---------------------------------
__global__ void __launch_bounds__(256)
count_kernel(const int* __restrict__ src, const int* __restrict__ dst) {
    int e = blockIdx.x * blockDim.x + threadIdx.x;
    if (e < Ee) {
        atomicAdd(&g_degout[src[e]], 1);
        atomicAdd(&g_degin[dst[e]], 1);
    }
}

// ---------------- chain A: x stats (float4) + last-block feat fold ----------
__global__ void __launch_bounds__(256)
stats_x_kernel(const float* __restrict__ x,
               const float* __restrict__ gamma, const float* __restrict__ beta,
               const float* __restrict__ W, const float* __restrict__ blin) {
    int t = threadIdx.x;
    int c4 = t & 31;
    int rg = t >> 5;
    float4 s = {0,0,0,0}, q = {0,0,0,0};
    for (int r = blockIdx.x * 8 + rg; r < Nn; r += STATX_BLOCKS * 8) {
        float4 v = *(const float4*)(x + (long)r * F_IN + 4 * c4);
        s.x += v.x; s.y += v.y; s.z += v.z; s.w += v.w;
        q.x += v.x * v.x; q.y += v.y * v.y;
        q.z += v.z * v.z; q.w += v.w * v.w;
    }
    __shared__ float4 shS[256], shQ[256];
    shS[t] = s; shQ[t] = q;
    __syncthreads();
    if (rg == 0) {
        #pragma unroll
        for (int j = 1; j < 8; j++) {
            float4 a = shS[j * 32 + c4], b = shQ[j * 32 + c4];
            s.x += a.x; s.y += a.y; s.z += a.z; s.w += a.w;
            q.x += b.x; q.y += b.y; q.z += b.z; q.w += b.w;
        }
        red_add_v4(g_sum + 4 * c4, s);
        red_add_v4(g_sumsq + 4 * c4, q);
    }
    // last block folds the feature BN into (g_Wp, g_c)
    __shared__ int sLast;
    __syncthreads();
    if (t == 0) sLast = last_block(STATX_BLOCKS) ? 1 : 0;
    __syncthreads();
    if (sLast)
        do_fold(gamma, beta, W, blin, F_IN, g_sum, g_sumsq,
                (float*)shS, (float*)shQ);
}

// ---------------- fused single-pass scan (decoupled lookback) + dis ---------
__global__ void __launch_bounds__(SCAN_T)
scan_dis_kernel() {
    __shared__ int sh[SCAN_T];
    __shared__ int s_base;
    int t = threadIdx.x, b = blockIdx.x;
    int base = b * SCAN_E + t * 4;
    int d0 = 0, d1 = 0, d2 = 0, d3 = 0;
    if (base + 0 < Nn) d0 = g_degin[base + 0];
    if (base + 1 < Nn) d1 = g_degin[base + 1];
    if (base + 2 < Nn) d2 = g_degin[base + 2];
    if (base + 3 < Nn) d3 = g_degin[base + 3];
    int tsum = d0 + d1 + d2 + d3;
    sh[t] = tsum; __syncthreads();
    for (int o = 1; o < SCAN_T; o <<= 1) {
        int v = (t >= o) ? sh[t - o] : 0;
        __syncthreads();
        sh[t] += v;
        __syncthreads();
    }
    if (t == SCAN_T - 1)
        atomicExch(&g_pub[b], (unsigned)sh[t] | 0x80000000u);
    if (t == 0) {
        int acc = 0;
        for (int j = 0; j < b; j++) {
            unsigned v;
            do { v = atomicAdd(&g_pub[j], 0u); } while (!(v & 0x80000000u));
            acc += (int)(v & 0x7fffffffu);
        }
        s_base = acc;
    }
    __syncthreads();
    int excl = sh[t] - tsum + s_base;
    int o0 = excl, o1 = o0 + d0, o2 = o1 + d1, o3 = o2 + d2;
    if (base + 0 < Nn) {
        g_off[base + 0] = o0; g_cursor[base + 0] = o0;
        g_dis[base + 0] = rsqrtf((float)(g_degout[base + 0] + 1));
    }
    if (base + 1 < Nn) {
        g_off[base + 1] = o1; g_cursor[base + 1] = o1;
        g_dis[base + 1] = rsqrtf((float)(g_degout[base + 1] + 1));
    }
    if (base + 2 < Nn) {
        g_off[base + 2] = o2; g_cursor[base + 2] = o2;
        g_dis[base + 2] = rsqrtf((float)(g_degout[base + 2] + 1));
    }
    if (base + 3 < Nn) {
        g_off[base + 3] = o3; g_cursor[base + 3] = o3;
        g_dis[base + 3] = rsqrtf((float)(g_degout[base + 3] + 1));
    }
    if (b == SCAN_NB - 1 && t == SCAN_T - 1)
        g_off[Nn] = s_base + sh[t];
}

// ---------------- fill CSR + restore zero invariants -------------------------
__global__ void __launch_bounds__(256)
fill_kernel(const int* __restrict__ src, const int* __restrict__ dst) {
    int e = blockIdx.x * blockDim.x + threadIdx.x;
    if (e < Ee) {
        int pos = atomicAdd(&g_cursor[dst[e]], 1);
        g_csr[pos] = src[e];
    }
    if (e < Nn) { g_degin[e] = 0; g_degout[e] = 0; }
    if (e < SCAN_NB) g_pub[e] = 0;
}

// ---------------- tiled GEMM: 128x64 tile, 8x4 register tiles ---------------
// FEAT : g_h = relu(A@Wp + c); stats -> g_s2/g_q2; last block folds layer 0.
// LAYER: g_zh = fp16( dis_row * (A@Wp + c) ).
template <int K, bool FEAT>
__global__ void __launch_bounds__(256, 2)
gemm_kernel(const float* __restrict__ A,
            const float* __restrict__ gammaN, const float* __restrict__ betaN,
            const float* __restrict__ WN) {
    __shared__ float As[128 * 64];   // 32 KB
    __shared__ float Wsm[64 * 64];   // 16 KB
    const int t  = threadIdx.x;
    const int tx = t & 15;
    const int ty = t >> 4;
    const int rowBase = blockIdx.x * 128;

    float4 acc[8];
    #pragma unroll
    for (int i = 0; i < 8; i++) acc[i] = make_float4(0.f, 0.f, 0.f, 0.f);

    for (int kt = 0; kt < K; kt += 64) {
        #pragma unroll
        for (int i = t; i < 128 * 16; i += 256) {
            int r = i >> 4, c4 = i & 15;
            int gr = rowBase + r;
            float4 v = {0,0,0,0};
            if (gr < Nn) v = *(const float4*)(A + (long)gr * K + kt + 4 * c4);
            ((float4*)As)[i] = v;
        }
        #pragma unroll
        for (int i = t; i < 64 * 16; i += 256) {
            int r = i >> 4, c4 = i & 15;
            ((float4*)Wsm)[i] = *(const float4*)(g_Wp + (long)(kt + r) * 64 + 4 * c4);
        }
        __syncthreads();

        #pragma unroll
        for (int k4 = 0; k4 < 16; k4++) {
            float4 w0 = ((const float4*)Wsm)[(4 * k4 + 0) * 16 + tx];
            float4 w1 = ((const float4*)Wsm)[(4 * k4 + 1) * 16 + tx];
            float4 w2 = ((const float4*)Wsm)[(4 * k4 + 2) * 16 + tx];
            float4 w3 = ((const float4*)Wsm)[(4 * k4 + 3) * 16 + tx];
            #pragma unroll
            for (int i = 0; i < 8; i++) {
                float4 a = ((const float4*)As)[(8 * ty + i) * 16 + k4];
                acc[i].x += a.x * w0.x; acc[i].y += a.x * w0.y;
                acc[i].z += a.x * w0.z; acc[i].w += a.x * w0.w;
                acc[i].x += a.y * w1.x; acc[i].y += a.y * w1.y;
                acc[i].z += a.y * w1.z; acc[i].w += a.y * w1.w;
                acc[i].x += a.z * w2.x; acc[i].y += a.z * w2.y;
                acc[i].z += a.z * w2.z; acc[i].w += a.z * w2.w;
                acc[i].x += a.w * w3.x; acc[i].y += a.w * w3.y;
                acc[i].z += a.w * w3.z; acc[i].w += a.w * w3.w;
            }
        }
        __syncthreads();
    }

    float4 cv = *(const float4*)(g_c + 4 * tx);
    float4 ls = {0,0,0,0}, lq = {0,0,0,0};
    #pragma unroll
    for (int i = 0; i < 8; i++) {
        int gr = rowBase + 8 * ty + i;
        if (gr >= Nn) continue;
        float4 v = acc[i];
        v.x += cv.x; v.y += cv.y; v.z += cv.z; v.w += cv.w;
        if (FEAT) {
            v.x = fmaxf(v.x, 0.f); v.y = fmaxf(v.y, 0.f);
            v.z = fmaxf(v.z, 0.f); v.w = fmaxf(v.w, 0.f);
            *(float4*)(g_h + (long)gr * 64 + 4 * tx) = v;
            ls.x += v.x; ls.y += v.y; ls.z += v.z; ls.w += v.w;
            lq.x += v.x * v.x; lq.y += v.y * v.y;
            lq.z += v.z * v.z; lq.w += v.w * v.w;
        } else {
            float di = __ldg(g_dis + gr);
            __half2 p0 = __floats2half2_rn(di * v.x, di * v.y);
            __half2 p1 = __floats2half2_rn(di * v.z, di * v.w);
            uint2 u;
            u.x = *(unsigned*)&p0;
            u.y = *(unsigned*)&p1;
            *(uint2*)(g_zh + (long)gr * 64 + 4 * tx) = u;
        }
    }
    if (FEAT) {
        __syncthreads();
        ((float4*)As)[t]       = ls;
        ((float4*)As)[256 + t] = lq;
        __syncthreads();
        if (ty == 0) {
            #pragma unroll
            for (int j = 1; j < 16; j++) {
                float4 a = ((float4*)As)[j * 16 + tx];
                float4 b = ((float4*)As)[256 + j * 16 + tx];
                ls.x += a.x; ls.y += a.y; ls.z += a.z; ls.w += a.w;
                lq.x += b.x; lq.y += b.y; lq.z += b.z; lq.w += b.w;
            }
            red_add_v4(g_s2 + 4 * tx, ls);
            red_add_v4(g_q2 + 4 * tx, lq);
        }
        // last block folds layer 0 (all blocks have finished reading g_Wp/g_c)
        __shared__ int sLast;
        __syncthreads();
        if (t == 0) sLast = last_block(GEMM_BLOCKS) ? 1 : 0;
        __syncthreads();
        if (sLast)
            do_fold(gammaN, betaN, WN, nullptr, HID, g_s2, g_q2, As, As + 64);
    }
}

// ---------------- CSR gather aggregation (fp16 zs, pre-scaled) --------------
// MODE 0: h -> g_h, stats -> g_s2/g_q2; last block folds the NEXT layer.
// MODE 1: pool into gout (by batch).
template <int MODE>
__global__ void __launch_bounds__(256)
gather_kernel(const float* __restrict__ bias,
              const int* __restrict__ batch,
              float* __restrict__ gout,
              const float* __restrict__ gammaN, const float* __restrict__ betaN,
              const float* __restrict__ WN) {
    const int t    = threadIdx.x;
    const int c    = t & 15;
    const int slot = t >> 4;
    const int i    = blockIdx.x * 16 + slot;
    float4 b4 = *(const float4*)(bias + 4 * c);
    float4 ls = {0,0,0,0}, lq = {0,0,0,0};

    if (i < Nn) {
        int st = __ldg(g_off + i), en = __ldg(g_off + i + 1);
        float di = __ldg(g_dis + i);
        const __half* zb = g_zh;
        float4 acc = h4_to_f4(__ldg((const uint2*)(zb + (long)i * 64) + c));
        int e = st;
        for (; e + 3 < en; e += 4) {
            int s0 = __ldg(g_csr + e + 0);
            int s1 = __ldg(g_csr + e + 1);
            int s2 = __ldg(g_csr + e + 2);
            int s3 = __ldg(g_csr + e + 3);
            uint2 u0 = __ldg((const uint2*)(zb + (long)s0 * 64) + c);
            uint2 u1 = __ldg((const uint2*)(zb + (long)s1 * 64) + c);
            uint2 u2 = __ldg((const uint2*)(zb + (long)s2 * 64) + c);
            uint2 u3 = __ldg((const uint2*)(zb + (long)s3 * 64) + c);
            float4 v0 = h4_to_f4(u0), v1 = h4_to_f4(u1);
            float4 v2 = h4_to_f4(u2), v3 = h4_to_f4(u3);
            acc.x += (v0.x + v1.x) + (v2.x + v3.x);
            acc.y += (v0.y + v1.y) + (v2.y + v3.y);
            acc.z += (v0.z + v1.z) + (v2.z + v3.z);
            acc.w += (v0.w + v1.w) + (v2.w + v3.w);
        }
        for (; e < en; e++) {
            int s = __ldg(g_csr + e);
            float4 v = h4_to_f4(__ldg((const uint2*)(zb + (long)s * 64) + c));
            acc.x += v.x; acc.y += v.y; acc.z += v.z; acc.w += v.w;
        }
        float4 h;
        h.x = fmaxf(di * acc.x + b4.x, 0.f);
        h.y = fmaxf(di * acc.y + b4.y, 0.f);
        h.z = fmaxf(di * acc.z + b4.z, 0.f);
        h.w = fmaxf(di * acc.w + b4.w, 0.f);
        if (MODE == 0) {
            *(float4*)(g_h + (long)i * 64 + 4 * c) = h;
            ls = h;
            lq.x = h.x * h.x; lq.y = h.y * h.y;
            lq.z = h.z * h.z; lq.w = h.w * h.w;
        } else {
            int g = __ldg(batch + i);
            red_add_v4(gout + (long)g * 64 + 4 * c, h);
        }
    }

    if (MODE == 0) {
        __shared__ float4 shS[256], shQ[256];
        shS[t] = ls; shQ[t] = lq;
        __syncthreads();
        if (slot == 0) {
            #pragma unroll
            for (int j = 1; j < 16; j++) {
                float4 a = shS[j * 16 + c], b = shQ[j * 16 + c];
                ls.x += a.x; ls.y += a.y; ls.z += a.z; ls.w += a.w;
                lq.x += b.x; lq.y += b.y; lq.z += b.z; lq.w += b.w;
            }
            red_add_v4(g_s2 + 4 * c, ls);
            red_add_v4(g_q2 + 4 * c, lq);
        }
        // last block folds the next layer's BN into (g_Wp, g_c)
        __shared__ int sLast;
        __syncthreads();
        if (t == 0) sLast = last_block(GATHER_GRID) ? 1 : 0;
        __syncthreads();
        if (sLast)
            do_fold(gammaN, betaN, WN, nullptr, HID, g_s2, g_q2,
                    (float*)shS, (float*)shQ);
    }
}

// ---------------- host-side symbol resolution --------------------------------
static float* sym_h() {
    static float* p = nullptr;
    if (!p) cudaGetSymbolAddress((void**)&p, g_h);
    return p;
}

// ---------------- launch ------------------------------------------------------
extern "C" void kernel_launch(void* const* d_in, const int* in_sizes, int n_in,
                              void* d_out, int out_size) {
    const float* x         = (const float*)d_in[0];
    const int*   ei        = (const int*)d_in[1];
    const int*   src       = ei;
    const int*   dst       = ei + Ee;
    const int*   batch     = (const int*)d_in[2];
    const float* bn_feat_g = (const float*)d_in[3];
    const float* bn_feat_b = (const float*)d_in[4];
    const float* W_feat    = (const float*)d_in[5];
    const float* b_feat    = (const float*)d_in[6];
    const float* bn_g      = (const float*)d_in[7];
    const float* bn_b      = (const float*)d_in[8];
    const float* Ws        = (const float*)d_in[9];
    const float* bs        = (const float*)d_in[10];
    float* gout = (float*)d_out;

    static cudaStream_t s2 = nullptr;
    static cudaEvent_t e0 = nullptr, eDis = nullptr, eCsr = nullptr;
    if (!s2) {
        cudaStreamCreateWithFlags(&s2, cudaStreamNonBlocking);
        cudaEventCreateWithFlags(&e0,   cudaEventDisableTiming);
        cudaEventCreateWithFlags(&eDis, cudaEventDisableTiming);
        cudaEventCreateWithFlags(&eCsr, cudaEventDisableTiming);
    }

    // ---- fork: chain B (CSR build + dis + gout zero) on s2 ----
    cudaEventRecord(e0, 0);
    cudaStreamWaitEvent(s2, e0, 0);
    cudaMemsetAsync(gout, 0, (size_t)Gg * HID * sizeof(float), s2);
    count_kernel<<<EDGE_BLOCKS, 256, 0, s2>>>(src, dst);
    scan_dis_kernel<<<SCAN_NB, SCAN_T, 0, s2>>>();
    cudaEventRecord(eDis, s2);                      // g_dis + g_off ready
    fill_kernel<<<EDGE_BLOCKS, 256, 0, s2>>>(src, dst);
    cudaEventRecord(eCsr, s2);                      // g_csr (+gout=0) ready

    // ---- chain A on main stream (folds fused into producers) ----
    stats_x_kernel<<<STATX_BLOCKS, 256>>>(x, bn_feat_g, bn_feat_b,
                                          W_feat, b_feat);
    gemm_kernel<F_IN, true><<<GEMM_BLOCKS, 256>>>(x, bn_g, bn_b, Ws);

    for (int i = 0; i < Ll; i++) {
        if (i == 0) cudaStreamWaitEvent(0, eDis, 0);   // epilogue needs dis
        gemm_kernel<HID, false><<<GEMM_BLOCKS, 256>>>(sym_h(), nullptr,
                                                      nullptr, nullptr);
        if (i == 0) cudaStreamWaitEvent(0, eCsr, 0);   // gather needs CSR
        if (i < Ll - 1)
            gather_kernel<0><<<GATHER_GRID, 256>>>(
                bs + i * HID, nullptr, nullptr,
                bn_g + (i + 1) * HID, bn_b + (i + 1) * HID,
                Ws + (long)(i + 1) * HID * HID);
        else
            gather_kernel<1><<<GATHER_GRID, 256>>>(
                bs + i * HID, batch, gout, nullptr, nullptr, nullptr);
    }
}

// round 14
// speedup vs baseline: 1.4140x; 1.4140x over previous
#include <cuda_runtime.h>
#include <cuda_fp16.h>
#include <mma.h>
using namespace nvcuda;

#define Nn   50000
#define Ee   800000
#define F_IN 128
#define HID  64
#define Ll   3
#define Gg   512
#define BN_EPS 1e-5f
#define INVN (1.0f / 50000.0f)

#define EDGE_BLOCKS  ((Ee + 255) / 256)            // 3125
#define STATX_BLOCKS 256
#define GEMM_BLOCKS  ((Nn + 127) / 128)            // 391
#define GATHER_GRID  ((Nn + 15) / 16)              // 3125
#define SCAN_T   512
#define SCAN_E   2048
#define SCAN_NB  ((Nn + SCAN_E - 1) / SCAN_E)      // 25

// ---------------- scratch (static device arrays; zero-initialized) ---------
__device__ __align__(16) __half g_h[Nn * HID];     // fp16 activations
__device__ __align__(16) __half g_zh[Nn * HID];    // dis-prescaled z, fp16
__device__ __align__(16) __half g_Wph[F_IN * HID]; // folded weight, fp16
__device__ __align__(16) float  g_c[HID];          // folded bias row
__device__ __align__(16) float  g_sum[F_IN];       // x stats (zero invariant)
__device__ __align__(16) float  g_sumsq[F_IN];
__device__ __align__(16) float  g_s2[HID];         // h stats (zero invariant)
__device__ __align__(16) float  g_q2[HID];
__device__ int      g_degout[Nn];                  // zero invariant
__device__ int      g_degin[Nn];                   // zero invariant
__device__ float    g_dis[Nn];
__device__ int      g_off[Nn + 1];
__device__ int      g_cursor[Nn];
__device__ int      g_csr[Ee];
__device__ unsigned g_pub[SCAN_NB];                // lookback (zero invariant)

// ---------------- helpers ----------------------------------------------------
__device__ __forceinline__ void red_add_v4(float* addr, float4 v) {
    asm volatile("red.global.add.v4.f32 [%0], {%1, %2, %3, %4};"
                 :: "l"(addr), "f"(v.x), "f"(v.y), "f"(v.z), "f"(v.w)
                 : "memory");
}

__device__ __forceinline__ float4 h4_to_f4(uint2 u) {
    __half2 a = *(__half2*)&u.x;
    __half2 b = *(__half2*)&u.y;
    float2 fa = __half22float2(a);
    float2 fb = __half22float2(b);
    return make_float4(fa.x, fa.y, fb.x, fb.y);
}

__device__ __forceinline__ uint2 f4_to_h4(float4 v) {
    __half2 p0 = __floats2half2_rn(v.x, v.y);
    __half2 p1 = __floats2half2_rn(v.z, v.w);
    uint2 u;
    u.x = *(unsigned*)&p0;
    u.y = *(unsigned*)&p1;
    return u;
}

// ---------------- chain B: edge degree count ---------------------------------
__global__ void __launch_bounds__(256)
count_kernel(const int* __restrict__ src, const int* __restrict__ dst) {
    int e = blockIdx.x * blockDim.x + threadIdx.x;
    if (e < Ee) {
        atomicAdd(&g_degout[src[e]], 1);
        atomicAdd(&g_degin[dst[e]], 1);
    }
}

// ---------------- chain A: x column stats (float4) ---------------------------
__global__ void __launch_bounds__(256)
stats_x_kernel(const float* __restrict__ x) {
    int t = threadIdx.x;
    int c4 = t & 31;
    int rg = t >> 5;
    float4 s = {0,0,0,0}, q = {0,0,0,0};
    for (int r = blockIdx.x * 8 + rg; r < Nn; r += STATX_BLOCKS * 8) {
        float4 v = *(const float4*)(x + (long)r * F_IN + 4 * c4);
        s.x += v.x; s.y += v.y; s.z += v.z; s.w += v.w;
        q.x += v.x * v.x; q.y += v.y * v.y;
        q.z += v.z * v.z; q.w += v.w * v.w;
    }
    __shared__ float4 shS[256], shQ[256];
    shS[t] = s; shQ[t] = q;
    __syncthreads();
    if (rg == 0) {
        #pragma unroll
        for (int j = 1; j < 8; j++) {
            float4 a = shS[j * 32 + c4], b = shQ[j * 32 + c4];
            s.x += a.x; s.y += a.y; s.z += a.z; s.w += a.w;
            q.x += b.x; q.y += b.y; q.z += b.z; q.w += b.w;
        }
        red_add_v4(g_sum + 4 * c4, s);
        red_add_v4(g_sumsq + 4 * c4, q);
    }
}

// ---------------- fused single-pass scan (decoupled lookback) + dis ---------
__global__ void __launch_bounds__(SCAN_T)
scan_dis_kernel() {
    __shared__ int sh[SCAN_T];
    __shared__ int s_base;
    int t = threadIdx.x, b = blockIdx.x;
    int base = b * SCAN_E + t * 4;
    int d0 = 0, d1 = 0, d2 = 0, d3 = 0;
    if (base + 0 < Nn) d0 = g_degin[base + 0];
    if (base + 1 < Nn) d1 = g_degin[base + 1];
    if (base + 2 < Nn) d2 = g_degin[base + 2];
    if (base + 3 < Nn) d3 = g_degin[base + 3];
    int tsum = d0 + d1 + d2 + d3;
    sh[t] = tsum; __syncthreads();
    for (int o = 1; o < SCAN_T; o <<= 1) {
        int v = (t >= o) ? sh[t - o] : 0;
        __syncthreads();
        sh[t] += v;
        __syncthreads();
    }
    if (t == SCAN_T - 1)
        atomicExch(&g_pub[b], (unsigned)sh[t] | 0x80000000u);
    if (t == 0) {
        int acc = 0;
        for (int j = 0; j < b; j++) {
            unsigned v;
            do { v = atomicAdd(&g_pub[j], 0u); } while (!(v & 0x80000000u));
            acc += (int)(v & 0x7fffffffu);
        }
        s_base = acc;
    }
    __syncthreads();
    int excl = sh[t] - tsum + s_base;
    int o0 = excl, o1 = o0 + d0, o2 = o1 + d1, o3 = o2 + d2;
    if (base + 0 < Nn) {
        g_off[base + 0] = o0; g_cursor[base + 0] = o0;
        g_dis[base + 0] = rsqrtf((float)(g_degout[base + 0] + 1));
    }
    if (base + 1 < Nn) {
        g_off[base + 1] = o1; g_cursor[base + 1] = o1;
        g_dis[base + 1] = rsqrtf((float)(g_degout[base + 1] + 1));
    }
    if (base + 2 < Nn) {
        g_off[base + 2] = o2; g_cursor[base + 2] = o2;
        g_dis[base + 2] = rsqrtf((float)(g_degout[base + 2] + 1));
    }
    if (base + 3 < Nn) {
        g_off[base + 3] = o3; g_cursor[base + 3] = o3;
        g_dis[base + 3] = rsqrtf((float)(g_degout[base + 3] + 1));
    }
    if (b == SCAN_NB - 1 && t == SCAN_T - 1)
        g_off[Nn] = s_base + sh[t];
}

// ---------------- fill CSR + restore zero invariants -------------------------
__global__ void __launch_bounds__(256)
fill_kernel(const int* __restrict__ src, const int* __restrict__ dst) {
    int e = blockIdx.x * blockDim.x + threadIdx.x;
    if (e < Ee) {
        int pos = atomicAdd(&g_cursor[dst[e]], 1);
        g_csr[pos] = src[e];
    }
    if (e < Nn) { g_degin[e] = 0; g_degout[e] = 0; }
    if (e < SCAN_NB) g_pub[e] = 0;
}

// ---------------- fold: BN -> (Wph fp16, c fp32); zero accumulators ---------
__global__ void __launch_bounds__(256)
fold_kernel(const float* __restrict__ gamma, const float* __restrict__ beta,
            const float* __restrict__ W, const float* __restrict__ blin,
            int K, int fromX) {
    __shared__ float s_s[F_IN], s_t[F_IN];
    int t = threadIdx.x;
    float* sums = fromX ? g_sum : g_s2;
    float* sqs  = fromX ? g_sumsq : g_q2;
    if (t < K) {
        float mu  = sums[t] * INVN;
        float var = fmaxf(sqs[t] * INVN - mu * mu, 0.f);
        float sc  = gamma[t] * rsqrtf(var + BN_EPS);
        s_s[t] = sc;
        s_t[t] = beta[t] - mu * sc;
        sums[t] = 0.f;
        sqs[t]  = 0.f;
    }
    __syncthreads();
    for (int i = t; i < K * HID; i += 256)
        g_Wph[i] = __float2half(s_s[i >> 6] * W[i]);
    if (t < HID) {
        float c = blin ? blin[t] : 0.f;
        for (int k = 0; k < K; k++) c += s_t[k] * W[k * HID + t];
        g_c[t] = c;
    }
}

// ---------------- WMMA GEMM: padded smem, fp16 in / fp32 accum --------------
// FEAT : stages fp32 x with in-flight fp16 convert; h -> g_h (fp16) + stats.
// LAYER: stages fp16 g_h; g_zh = fp16(dis_row * (A@W + c)).
template <int K, bool FEAT>
__global__ void __launch_bounds__(256)
gemm_kernel(const void* __restrict__ Ain) {
    constexpr int LDA = K + 8;        // halves
    constexpr int LDB = 72;           // halves
    constexpr int LDO = 72;           // floats
    extern __shared__ __align__(32) char smem[];
    __half* As   = (__half*)smem;                 // 128 x LDA
    __half* Wsm  = As + 128 * LDA;                // K x LDB
    float*  outS = (float*)smem;                  // 128 x LDO (after sync)

    const int t  = threadIdx.x;
    const int w  = t >> 5;             // warp 0..7 -> rows [16w,16w+16)
    const int rowBase = blockIdx.x * 128;

    // ---- stage A ----
    if (FEAT) {
        const float* A = (const float*)Ain;
        const int n4 = 128 * K / 4;    // float4 chunks (4 cols each)
        for (int i = t; i < n4; i += 256) {
            int r  = i / (K / 4);
            int c4 = i % (K / 4);
            int gr = rowBase + r;
            float4 v = {0, 0, 0, 0};
            if (gr < Nn) v = *(const float4*)(A + (long)gr * K + 4 * c4);
            *(uint2*)(As + r * LDA + 4 * c4) = f4_to_h4(v);
        }
    } else {
        const __half* A = (const __half*)Ain;
        const int n8 = 128 * K / 8;    // uint4 chunks (8 halves)
        for (int i = t; i < n8; i += 256) {
            int r  = i / (K / 8);
            int c8 = i % (K / 8);
            int gr = rowBase + r;
            uint4 v = {0, 0, 0, 0};
            if (gr < Nn) v = *(const uint4*)(A + (long)gr * K + 8 * c8);
            *(uint4*)(As + r * LDA + 8 * c8) = v;
        }
    }
    // ---- stage W (K x 64 -> padded LDB) ----
    {
        const int n8 = K * 64 / 8;
        for (int i = t; i < n8; i += 256) {
            int r  = i >> 3;           // 8 uint4 per row
            int c8 = i & 7;
            *(uint4*)(Wsm + r * LDB + 8 * c8) =
                *(const uint4*)(g_Wph + r * 64 + 8 * c8);
        }
    }
    __syncthreads();

    wmma::fragment<wmma::accumulator, 16, 16, 16, float> acc[4];
    #pragma unroll
    for (int n = 0; n < 4; n++) wmma::fill_fragment(acc[n], 0.f);

    #pragma unroll
    for (int k = 0; k < K; k += 16) {
        wmma::fragment<wmma::matrix_a, 16, 16, 16, __half, wmma::row_major> af;
        wmma::load_matrix_sync(af, As + 16 * w * LDA + k, LDA);
        #pragma unroll
        for (int n = 0; n < 4; n++) {
            wmma::fragment<wmma::matrix_b, 16, 16, 16, __half, wmma::row_major> bf;
            wmma::load_matrix_sync(bf, Wsm + k * LDB + 16 * n, LDB);
            wmma::mma_sync(acc[n], af, bf, acc[n]);
        }
    }
    __syncthreads();   // As/Wsm dead; smem becomes outS
    #pragma unroll
    for (int n = 0; n < 4; n++)
        wmma::store_matrix_sync(outS + 16 * w * LDO + 16 * n, acc[n], LDO,
                                wmma::mem_row_major);
    __syncthreads();

    // ---- epilogue: tx = col group (4 cols), ty = row group (8 rows) ----
    const int tx = t & 15;
    const int ty = t >> 4;
    float4 cv = *(const float4*)(g_c + 4 * tx);
    float4 ls = {0,0,0,0}, lq = {0,0,0,0};
    #pragma unroll
    for (int i = 0; i < 8; i++) {
        int gr = rowBase + 8 * ty + i;
        if (gr >= Nn) continue;
        float4 v = *(const float4*)(outS + (8 * ty + i) * LDO + 4 * tx);
        v.x += cv.x; v.y += cv.y; v.z += cv.z; v.w += cv.w;
        if (FEAT) {
            v.x = fmaxf(v.x, 0.f); v.y = fmaxf(v.y, 0.f);
            v.z = fmaxf(v.z, 0.f); v.w = fmaxf(v.w, 0.f);
            *(uint2*)(g_h + (long)gr * 64 + 4 * tx) = f4_to_h4(v);
            ls.x += v.x; ls.y += v.y; ls.z += v.z; ls.w += v.w;
            lq.x += v.x * v.x; lq.y += v.y * v.y;
            lq.z += v.z * v.z; lq.w += v.w * v.w;
        } else {
            float di = __ldg(g_dis + gr);
            v.x *= di; v.y *= di; v.z *= di; v.w *= di;
            *(uint2*)(g_zh + (long)gr * 64 + 4 * tx) = f4_to_h4(v);
        }
    }
    if (FEAT) {   // block-reduce stats (reuse outS after barrier)
        __syncthreads();
        ((float4*)outS)[t]       = ls;
        ((float4*)outS)[256 + t] = lq;
        __syncthreads();
        if (ty == 0) {
            #pragma unroll
            for (int j = 1; j < 16; j++) {
                float4 a = ((float4*)outS)[j * 16 + tx];
                float4 b = ((float4*)outS)[256 + j * 16 + tx];
                ls.x += a.x; ls.y += a.y; ls.z += a.z; ls.w += a.w;
                lq.x += b.x; lq.y += b.y; lq.z += b.z; lq.w += b.w;
            }
            red_add_v4(g_s2 + 4 * tx, ls);
            red_add_v4(g_q2 + 4 * tx, lq);
        }
    }
}

// ---------------- CSR gather aggregation (fp16 zs, pre-scaled) --------------
template <int MODE>
__global__ void __launch_bounds__(256)
gather_kernel(const float* __restrict__ bias,
              const int* __restrict__ batch,
              float* __restrict__ gout) {
    const int t    = threadIdx.x;
    const int c    = t & 15;
    const int slot = t >> 4;
    const int i    = blockIdx.x * 16 + slot;
    float4 b4 = *(const float4*)(bias + 4 * c);
    float4 ls = {0,0,0,0}, lq = {0,0,0,0};

    if (i < Nn) {
        int st = __ldg(g_off + i), en = __ldg(g_off + i + 1);
        float di = __ldg(g_dis + i);
        const __half* zb = g_zh;
        float4 acc = h4_to_f4(__ldg((const uint2*)(zb + (long)i * 64) + c));
        int e = st;
        for (; e + 3 < en; e += 4) {
            int s0 = __ldg(g_csr + e + 0);
            int s1 = __ldg(g_csr + e + 1);
            int s2 = __ldg(g_csr + e + 2);
            int s3 = __ldg(g_csr + e + 3);
            uint2 u0 = __ldg((const uint2*)(zb + (long)s0 * 64) + c);
            uint2 u1 = __ldg((const uint2*)(zb + (long)s1 * 64) + c);
            uint2 u2 = __ldg((const uint2*)(zb + (long)s2 * 64) + c);
            uint2 u3 = __ldg((const uint2*)(zb + (long)s3 * 64) + c);
            float4 v0 = h4_to_f4(u0), v1 = h4_to_f4(u1);
            float4 v2 = h4_to_f4(u2), v3 = h4_to_f4(u3);
            acc.x += (v0.x + v1.x) + (v2.x + v3.x);
            acc.y += (v0.y + v1.y) + (v2.y + v3.y);
            acc.z += (v0.z + v1.z) + (v2.z + v3.z);
            acc.w += (v0.w + v1.w) + (v2.w + v3.w);
        }
        for (; e < en; e++) {
            int s = __ldg(g_csr + e);
            float4 v = h4_to_f4(__ldg((const uint2*)(zb + (long)s * 64) + c));
            acc.x += v.x; acc.y += v.y; acc.z += v.z; acc.w += v.w;
        }
        float4 h;
        h.x = fmaxf(di * acc.x + b4.x, 0.f);
        h.y = fmaxf(di * acc.y + b4.y, 0.f);
        h.z = fmaxf(di * acc.z + b4.z, 0.f);
        h.w = fmaxf(di * acc.w + b4.w, 0.f);
        if (MODE == 0) {
            *(uint2*)(g_h + (long)i * 64 + 4 * c) = f4_to_h4(h);
            ls = h;
            lq.x = h.x * h.x; lq.y = h.y * h.y;
            lq.z = h.z * h.z; lq.w = h.w * h.w;
        } else {
            int g = __ldg(batch + i);
            red_add_v4(gout + (long)g * 64 + 4 * c, h);
        }
    }

    if (MODE == 0) {
        __shared__ float4 shS[256], shQ[256];
        shS[t] = ls; shQ[t] = lq;
        __syncthreads();
        if (slot == 0) {
            #pragma unroll
            for (int j = 1; j < 16; j++) {
                float4 a = shS[j * 16 + c], b = shQ[j * 16 + c];
                ls.x += a.x; ls.y += a.y; ls.z += a.z; ls.w += a.w;
                lq.x += b.x; lq.y += b.y; lq.z += b.z; lq.w += b.w;
            }
            red_add_v4(g_s2 + 4 * c, ls);
            red_add_v4(g_q2 + 4 * c, lq);
        }
    }
}

// ---------------- host-side symbol resolution --------------------------------
static __half* sym_h16() {
    static __half* p = nullptr;
    if (!p) cudaGetSymbolAddress((void**)&p, g_h);
    return p;
}

// ---------------- launch ------------------------------------------------------
extern "C" void kernel_launch(void* const* d_in, const int* in_sizes, int n_in,
                              void* d_out, int out_size) {
    const float* x         = (const float*)d_in[0];
    const int*   ei        = (const int*)d_in[1];
    const int*   src       = ei;
    const int*   dst       = ei + Ee;
    const int*   batch     = (const int*)d_in[2];
    const float* bn_feat_g = (const float*)d_in[3];
    const float* bn_feat_b = (const float*)d_in[4];
    const float* W_feat    = (const float*)d_in[5];
    const float* b_feat    = (const float*)d_in[6];
    const float* bn_g      = (const float*)d_in[7];
    const float* bn_b      = (const float*)d_in[8];
    const float* Ws        = (const float*)d_in[9];
    const float* bs        = (const float*)d_in[10];
    float* gout = (float*)d_out;

    // smem sizes: max(A+W staging, fp32 out staging)
    static const size_t SM_FEAT =
        ((size_t)128 * (F_IN + 8) * 2 + (size_t)F_IN * 72 * 2 > 128 * 72 * 4)
        ? (size_t)128 * (F_IN + 8) * 2 + (size_t)F_IN * 72 * 2
        : (size_t)128 * 72 * 4;                                   // 53248
    static const size_t SM_LAYER =
        ((size_t)128 * (HID + 8) * 2 + (size_t)HID * 72 * 2 > 128 * 72 * 4)
        ? (size_t)128 * (HID + 8) * 2 + (size_t)HID * 72 * 2
        : (size_t)128 * 72 * 4;                                   // 36864

    static cudaStream_t s2 = nullptr;
    static cudaEvent_t e0 = nullptr, eDis = nullptr, eCsr = nullptr;
    if (!s2) {
        cudaStreamCreateWithFlags(&s2, cudaStreamNonBlocking);
        cudaEventCreateWithFlags(&e0,   cudaEventDisableTiming);
        cudaEventCreateWithFlags(&eDis, cudaEventDisableTiming);
        cudaEventCreateWithFlags(&eCsr, cudaEventDisableTiming);
        cudaFuncSetAttribute(gemm_kernel<F_IN, true>,
            cudaFuncAttributeMaxDynamicSharedMemorySize, (int)SM_FEAT);
        cudaFuncSetAttribute(gemm_kernel<HID, false>,
            cudaFuncAttributeMaxDynamicSharedMemorySize, (int)SM_LAYER);
    }

    // ---- fork: chain B (CSR build + dis + gout zero) on s2 ----
    cudaEventRecord(e0, 0);
    cudaStreamWaitEvent(s2, e0, 0);
    cudaMemsetAsync(gout, 0, (size_t)Gg * HID * sizeof(float), s2);
    count_kernel<<<EDGE_BLOCKS, 256, 0, s2>>>(src, dst);
    scan_dis_kernel<<<SCAN_NB, SCAN_T, 0, s2>>>();
    cudaEventRecord(eDis, s2);                      // g_dis + g_off ready
    fill_kernel<<<EDGE_BLOCKS, 256, 0, s2>>>(src, dst);
    cudaEventRecord(eCsr, s2);                      // g_csr (+gout=0) ready

    // ---- chain A on main stream ----
    stats_x_kernel<<<STATX_BLOCKS, 256>>>(x);
    fold_kernel<<<1, 256>>>(bn_feat_g, bn_feat_b, W_feat, b_feat, F_IN, 1);
    gemm_kernel<F_IN, true><<<GEMM_BLOCKS, 256, SM_FEAT>>>(x);

    for (int i = 0; i < Ll; i++) {
        fold_kernel<<<1, 256>>>(bn_g + i * HID, bn_b + i * HID,
                                Ws + (long)i * HID * HID, nullptr, HID, 0);
        if (i == 0) cudaStreamWaitEvent(0, eDis, 0);   // epilogue needs dis
        gemm_kernel<HID, false><<<GEMM_BLOCKS, 256, SM_LAYER>>>(sym_h16());
        if (i == 0) cudaStreamWaitEvent(0, eCsr, 0);   // gather needs CSR
        if (i < Ll - 1)
            gather_kernel<0><<<GATHER_GRID, 256>>>(bs + i * HID, nullptr,
                                                   nullptr);
        else
            gather_kernel<1><<<GATHER_GRID, 256>>>(bs + i * HID, batch, gout);
    }
}